// round 16
// baseline (speedup 1.0000x reference)
#include <cuda_runtime.h>
#include <cstdint>

#define FULLMASK 0xffffffffu
typedef unsigned long long ull;

static constexpr int Hh     = 5;
static constexpr int Tt     = 512;
static constexpr int Bb     = 8192;
static constexpr int CHUNK  = 8;            // timesteps per smem chunk
static constexpr int NCHUNK = Tt / CHUNK;   // 64
static constexpr int EPW    = 16;           // elements per warp (2 lanes each)
static constexpr int BLOCK  = 32;
static constexpr int GRID   = Bb / EPW;     // 512 (exact)
static constexpr int ROWF   = Tt * Hh;      // 2560
static constexpr int CH_FL  = CHUNK * Hh;   // 40 floats per element per chunk

// ---------- packed f32x2 helpers ----------
__device__ __forceinline__ ull pack2(float lo, float hi) {
    ull r; asm("mov.b64 %0, {%1, %2};" : "=l"(r) : "f"(lo), "f"(hi)); return r;
}
__device__ __forceinline__ void unpack2(ull v, float& lo, float& hi) {
    asm("mov.b64 {%0, %1}, %2;" : "=f"(lo), "=f"(hi) : "l"(v));
}
__device__ __forceinline__ ull fma2(ull a, ull b, ull c) {
    ull d; asm("fma.rn.f32x2 %0, %1, %2, %3;" : "=l"(d) : "l"(a), "l"(b), "l"(c));
    return d;
}
// volatile variants: pin the hand-interleaved schedule
__device__ __forceinline__ ull fma2v(ull a, ull b, ull c) {
    ull d; asm volatile("fma.rn.f32x2 %0, %1, %2, %3;" : "=l"(d) : "l"(a), "l"(b), "l"(c));
    return d;
}
__device__ __forceinline__ float tanhv(float x) {
    float y; asm volatile("tanh.approx.f32 %0, %1;" : "=f"(y) : "f"(x)); return y;
}

// ============================================================================
// Fused LSTM + head. One warp/CTA, 16 elements, 2 lanes/element.
// lane = 2*e + role.  role0 owns pair-rows (i_s, g_s), role1 owns (f_s, o_s).
// Both lanes redundantly carry REAL c_s and hs_s = 2*h_s (R15 scheme):
//   T0 = tanh(z.lo) [Ti|Tf], T1 = tanh(z.hi) [Tg|To]
//   pu = fma(T0, X, X), X = role?c:T1  -> p=2ig | u=2fc
//   q  = bfly(pu,1) ; c' = 0.5*pu + 0.5*q  (identical both lanes)
//   w2 = bfly(T1,1) ; hs = fma(role?T1:w2, Tc, Tc), Tc = tanh(c')
// Folding: W_ih i/f/o *0.5, g *1 ; W_hh i/f/o *0.25, g *0.5 ; hs = 2h.
//
// R16: SOFTWARE PIPELINE. Step t's MUFU stalls are filled with step t+1's
// x-projection (independent 25 fma2), schedule pinned by asm volatile.
// Accumulators double-buffered (A/B); x chunks staged 2 ahead.
// ============================================================================
__global__ void __launch_bounds__(BLOCK)
fused_kernel(const float* __restrict__ x,
             const float* __restrict__ W_ih, const float* __restrict__ W_hh,
             const float* __restrict__ b_ih, const float* __restrict__ b_hh,
             const float* __restrict__ W1, const float* __restrict__ b1,
             const float* __restrict__ W2, const float* __restrict__ b2,
             const float* __restrict__ W3, const float* __restrict__ b3,
             float* __restrict__ out)
{
    __shared__ __align__(16) ull sx[2][CHUNK][EPW][6];  // padded: 12288 B
    __shared__ float sW1[32 * 5], sb1[32], sb2[32], sb3[5];
    __shared__ float sW2[32 * 33];            // padded rows
    __shared__ float sW3[5 * 33];
    __shared__ float hres[EPW * Hh];

    const int lane = threadIdx.x;
    const int e    = lane >> 1;
    const int role = lane & 1;

    const int base = blockIdx.x * EPW;
    const int gb   = base + e;

    // ---- per-lane packed weights ----
    const int rlo = 5 * role;                 // +0 | +5   (i_s | f_s)
    const int rhi = 10 + 5 * role;            // +10 | +15 (g_s | o_s)
    const float xhi = role ? 0.5f : 1.0f;
    const float hhi = role ? 0.25f : 0.5f;

    ull wx[5][5], wh[5][5], bias[5];
#pragma unroll
    for (int s = 0; s < 5; ++s) {
#pragma unroll
        for (int k = 0; k < 5; ++k) {
            wx[s][k] = pack2(0.50f * W_ih[(s + rlo) * 5 + k],
                             xhi   * W_ih[(s + rhi) * 5 + k]);
            wh[s][k] = pack2(0.25f * W_hh[(s + rlo) * 5 + k],
                             hhi   * W_hh[(s + rhi) * 5 + k]);
        }
        bias[s] = pack2(0.5f * (b_ih[s + rlo] + b_hh[s + rlo]),
                        xhi  * (b_ih[s + rhi] + b_hh[s + rhi]));
    }

    // ---- head weights to smem (one-time) ----
    for (int i = lane; i < 160; i += BLOCK) sW1[i] = W1[i];
    for (int i = lane; i < 1024; i += BLOCK) sW2[(i >> 5) * 33 + (i & 31)] = W2[i];
    for (int i = lane; i < 160; i += BLOCK) sW3[(i >> 5) * 33 + (i & 31)] = W3[i];
    if (lane < 32) { sb1[lane] = b1[lane]; sb2[lane] = b2[lane]; }
    if (lane < 5)  sb3[lane] = b3[lane];

    // ---- staging: lane covers floats [role*20, role*20+20) of its element ----
    const int lo = role * 20;

#define STAGE_LDG(C)                                                          \
    do { const float* src = x + gb * ROWF + (C) * CH_FL + lo;                 \
        pf0 = *(const float4*)(src);                                          \
        pf1 = *(const float4*)(src + 4);                                      \
        pf2 = *(const float4*)(src + 8);                                      \
        pf3 = *(const float4*)(src + 12);                                     \
        pf4 = *(const float4*)(src + 16);                                     \
    } while (0)

#define STAGE_STS(BUF)                                                        \
    do { const float* ap[5] = {&pf0.x, &pf1.x, &pf2.x, &pf3.x, &pf4.x};       \
        _Pragma("unroll")                                                     \
        for (int j = 0; j < 20; ++j) {                                        \
            const float v = ap[j >> 2][j & 3];                                \
            const int f = lo + j, t = f / 5, k = f - 5 * t;                   \
            sx[BUF][t][e][k] = pack2(v, v); }                                 \
    } while (0)

#define XP(BUF, TL) (&sx[BUF][TL][e][0])

// h-projection op (volatile, on chain)
#define HP(A_, S, K) A_[S] = fma2v(wh[S][K], _hd[K], A_[S])
// next-step x-projection op (volatile, the filler)
#define NX(A_, S, K) A_[S] = fma2v(wx[S][K], _xn[K], A_[S])

// ---- one recurrence step, hand-interleaved ----
#define STEP(CUR, NXT, XN)                                                    \
do {                                                                          \
    const ulonglong2 _n01 = *(const ulonglong2*)(XN);                         \
    const ulonglong2 _n23 = *(const ulonglong2*)((XN) + 2);                   \
    const ull _xn[5] = {_n01.x, _n01.y, _n23.x, _n23.y, (XN)[4]};             \
    ull _hd[5];                                                               \
    _hd[0] = pack2(hs[0], hs[0]); _hd[1] = pack2(hs[1], hs[1]);               \
    _hd[2] = pack2(hs[2], hs[2]); _hd[3] = pack2(hs[3], hs[3]);               \
    _hd[4] = pack2(hs[4], hs[4]);                                             \
    HP(CUR,0,0); HP(CUR,1,0); HP(CUR,2,0); HP(CUR,3,0); HP(CUR,4,0);          \
    HP(CUR,0,1); HP(CUR,1,1); HP(CUR,2,1); HP(CUR,3,1); HP(CUR,4,1);          \
    HP(CUR,0,2); HP(CUR,1,2); HP(CUR,2,2); HP(CUR,3,2); HP(CUR,4,2);          \
    HP(CUR,0,3); HP(CUR,1,3); HP(CUR,2,3); HP(CUR,3,3); HP(CUR,4,3);          \
    HP(CUR,0,4); HP(CUR,1,4); HP(CUR,2,4); HP(CUR,3,4); HP(CUR,4,4);          \
    float _z0[5], _z1[5];                                                     \
    unpack2(CUR[0], _z0[0], _z1[0]); unpack2(CUR[1], _z0[1], _z1[1]);         \
    unpack2(CUR[2], _z0[2], _z1[2]); unpack2(CUR[3], _z0[3], _z1[3]);         \
    unpack2(CUR[4], _z0[4], _z1[4]);                                          \
    NXT[0] = bias[0]; NXT[1] = bias[1]; NXT[2] = bias[2];                     \
    NXT[3] = bias[3]; NXT[4] = bias[4];                                       \
    float _T0[5], _T1[5], _w2[5];                                             \
    /* region A: 10 tanh, each shadowing independent NXT fma2 / shfl */       \
    _T0[0] = tanhv(_z0[0]); NX(NXT,0,0); NX(NXT,1,0);                         \
    _T1[0] = tanhv(_z1[0]); NX(NXT,2,0);                                      \
    _w2[0] = __shfl_xor_sync(FULLMASK, _T1[0], 1);                            \
    _T0[1] = tanhv(_z0[1]); NX(NXT,3,0); NX(NXT,4,0);                         \
    _T1[1] = tanhv(_z1[1]); NX(NXT,0,1);                                      \
    _w2[1] = __shfl_xor_sync(FULLMASK, _T1[1], 1);                            \
    _T0[2] = tanhv(_z0[2]); NX(NXT,1,1); NX(NXT,2,1);                         \
    _T1[2] = tanhv(_z1[2]); NX(NXT,3,1);                                      \
    _w2[2] = __shfl_xor_sync(FULLMASK, _T1[2], 1);                            \
    _T0[3] = tanhv(_z0[3]); NX(NXT,4,1); NX(NXT,0,2);                         \
    _T1[3] = tanhv(_z1[3]); NX(NXT,1,2);                                      \
    _w2[3] = __shfl_xor_sync(FULLMASK, _T1[3], 1);                            \
    _T0[4] = tanhv(_z0[4]); NX(NXT,2,2); NX(NXT,3,2);                         \
    _T1[4] = tanhv(_z1[4]); NX(NXT,4,2);                                      \
    _w2[4] = __shfl_xor_sync(FULLMASK, _T1[4], 1);                            \
    /* region B: pu / bfly / c, with k=3 fillers */                           \
    float _pu[5], _q[5];                                                      \
    { const float _X = role ? c[0] : _T1[0]; _pu[0] = fmaf(_T0[0], _X, _X); } \
    NX(NXT,0,3);                                                              \
    { const float _X = role ? c[1] : _T1[1]; _pu[1] = fmaf(_T0[1], _X, _X); } \
    NX(NXT,1,3);                                                              \
    { const float _X = role ? c[2] : _T1[2]; _pu[2] = fmaf(_T0[2], _X, _X); } \
    NX(NXT,2,3);                                                              \
    { const float _X = role ? c[3] : _T1[3]; _pu[3] = fmaf(_T0[3], _X, _X); } \
    NX(NXT,3,3);                                                              \
    { const float _X = role ? c[4] : _T1[4]; _pu[4] = fmaf(_T0[4], _X, _X); } \
    NX(NXT,4,3);                                                              \
    _q[0] = __shfl_xor_sync(FULLMASK, _pu[0], 1);                             \
    _q[1] = __shfl_xor_sync(FULLMASK, _pu[1], 1);                             \
    _q[2] = __shfl_xor_sync(FULLMASK, _pu[2], 1);                             \
    _q[3] = __shfl_xor_sync(FULLMASK, _pu[3], 1);                             \
    _q[4] = __shfl_xor_sync(FULLMASK, _pu[4], 1);                             \
    c[0] = fmaf(0.5f, _pu[0], 0.5f * _q[0]);                                  \
    c[1] = fmaf(0.5f, _pu[1], 0.5f * _q[1]);                                  \
    c[2] = fmaf(0.5f, _pu[2], 0.5f * _q[2]);                                  \
    c[3] = fmaf(0.5f, _pu[3], 0.5f * _q[3]);                                  \
    c[4] = fmaf(0.5f, _pu[4], 0.5f * _q[4]);                                  \
    /* region C: 5 tanh shadowing k=4 fillers */                              \
    { const float _Tc = tanhv(c[0]); NX(NXT,0,4);                             \
      hs[0] = fmaf(role ? _T1[0] : _w2[0], _Tc, _Tc); }                       \
    { const float _Tc = tanhv(c[1]); NX(NXT,1,4);                             \
      hs[1] = fmaf(role ? _T1[1] : _w2[1], _Tc, _Tc); }                       \
    { const float _Tc = tanhv(c[2]); NX(NXT,2,4);                             \
      hs[2] = fmaf(role ? _T1[2] : _w2[2], _Tc, _Tc); }                       \
    { const float _Tc = tanhv(c[3]); NX(NXT,3,4);                             \
      hs[3] = fmaf(role ? _T1[3] : _w2[3], _Tc, _Tc); }                       \
    { const float _Tc = tanhv(c[4]); NX(NXT,4,4);                             \
      hs[4] = fmaf(role ? _T1[4] : _w2[4], _Tc, _Tc); }                       \
} while (0)

    // ---- prologue: stage chunks 0 and 1 ----
    float4 pf0, pf1, pf2, pf3, pf4;
    STAGE_LDG(0); STAGE_STS(0);
    STAGE_LDG(1); STAGE_STS(1);
    __syncwarp();

    float c[5]  = {0.f, 0.f, 0.f, 0.f, 0.f};   // REAL c on both lanes
    float hs[5] = {0.f, 0.f, 0.f, 0.f, 0.f};   // REAL 2*h on both lanes

    // initial A = bias + Wx * x(t=0)
    ull A[5], B[5];
    {
        const ull* xr = XP(0, 0);
        const ulonglong2 x01 = *(const ulonglong2*)(xr);
        const ulonglong2 x23 = *(const ulonglong2*)(xr + 2);
        const ull xv[5] = {x01.x, x01.y, x23.x, x23.y, xr[4]};
#pragma unroll
        for (int s = 0; s < 5; ++s) {
            A[s] = bias[s];
#pragma unroll
            for (int k = 0; k < 5; ++k) A[s] = fma2(wx[s][k], xv[k], A[s]);
        }
    }

    for (int ch = 0; ch < NCHUNK; ++ch) {
        if (ch + 2 < NCHUNK) STAGE_LDG(ch + 2);
        const int buf = ch & 1;

        STEP(A, B, XP(buf, 1));
        STEP(B, A, XP(buf, 2));
        STEP(A, B, XP(buf, 3));
        STEP(B, A, XP(buf, 4));
        STEP(A, B, XP(buf, 5));
        STEP(B, A, XP(buf, 6));
        STEP(A, B, XP(buf, 7));
        STEP(B, A, XP(buf ^ 1, 0));   // last chunk: builds unused garbage A

        if (ch + 2 < NCHUNK) STAGE_STS(buf);
        __syncwarp();
    }

    // ==================== fused head ====================
    if (role == 1) {
#pragma unroll
        for (int s = 0; s < 5; ++s)
            hres[e * Hh + s] = 0.5f * hs[s] + x[gb * ROWF + (Tt - 1) * Hh + s];
    }
    __syncwarp();

#pragma unroll 4
    for (int ee = 0; ee < EPW; ++ee) {
        const int g = base + ee;
        float a1 = sb1[lane];
#pragma unroll
        for (int k = 0; k < 5; ++k)
            a1 = fmaf(sW1[lane * 5 + k], hres[ee * Hh + k], a1);
        a1 = fmaxf(a1, 0.0f);

        float a2 = sb2[lane];
#pragma unroll
        for (int k = 0; k < 32; ++k)
            a2 = fmaf(sW2[lane * 33 + k], __shfl_sync(FULLMASK, a1, k), a2);
        a2 = fmaxf(a2, 0.0f);

        const int wrow = (lane < 5) ? lane : 0;
        float o = (lane < 5) ? sb3[lane] : 0.0f;
#pragma unroll
        for (int k = 0; k < 32; ++k)
            o = fmaf(sW3[wrow * 33 + k], __shfl_sync(FULLMASK, a2, k), o);

        if (lane < 5) out[g * Hh + lane] = o;
    }

#undef STAGE_LDG
#undef STAGE_STS
#undef XP
#undef HP
#undef NX
#undef STEP
}

// ============================================================================
extern "C" void kernel_launch(void* const* d_in, const int* in_sizes, int n_in,
                              void* d_out, int out_size) {
    const float* x    = (const float*)d_in[0];
    const float* W_ih = (const float*)d_in[1];
    const float* W_hh = (const float*)d_in[2];
    const float* b_ih = (const float*)d_in[3];
    const float* b_hh = (const float*)d_in[4];
    const float* W1   = (const float*)d_in[5];
    const float* b1   = (const float*)d_in[6];
    const float* W2   = (const float*)d_in[7];
    const float* b2   = (const float*)d_in[8];
    const float* W3   = (const float*)d_in[9];
    const float* b3   = (const float*)d_in[10];
    float* out = (float*)d_out;

    fused_kernel<<<GRID, BLOCK>>>(x, W_ih, W_hh, b_ih, b_hh,
                                  W1, b1, W2, b2, W3, b3, out);
    (void)in_sizes; (void)n_in; (void)out_size;
}